// round 16
// baseline (speedup 1.0000x reference)
#include <cuda_runtime.h>
#include <cuda_fp16.h>
#include <cstdint>

// Problem dims (fixed): X:(B,N), boundaries:(N,K+1), weight:(N,K,E), bias:(N,E)
#define BDIM 4096
#define NDIM 64
#define KDIM 128
#define EDIM 512
#define EPS_F 1e-8f
#define BROW (KDIM + 1)              // 129

#define GROUP_K 8                    // k-rows per TMA group
#define NGROUPS (KDIM / GROUP_K)     // 16
#define GBYTES (GROUP_K * EDIM * 4)  // 16 KB per group
#define SMEM_DYN (2 * GBYTES + 16)   // double buffer + mbarriers

#define PREFIX_BLOCKS NDIM                         // 64 (one n each)
#define SEARCH_BLOCKS ((BDIM * NDIM) / 256)        // 1024

// Prefix table T[n][k][e] (fp16): T[n][k][e] = bias[n][e] + sum_{j<k} w[n][j][e]
// out[b][n][e] = relu( lerp(T[n][bidx], T[n][bidx+1], frac) )
__device__ __half g_T16[(size_t)NDIM * BROW * EDIM];
// Per-(b,n) (frac, bidx), indexed b*N+n.
__device__ float2 g_SF[(size_t)BDIM * NDIM];

__device__ __forceinline__ uint32_t smem_u32(const void* p) {
    uint32_t a;
    asm("{ .reg .u64 t; cvta.to.shared.u64 t, %1; cvt.u32.u64 %0, t; }"
        : "=r"(a) : "l"(p));
    return a;
}

__device__ __forceinline__ void mbar_init(uint32_t mbar, uint32_t cnt) {
    asm volatile("mbarrier.init.shared.b64 [%0], %1;" :: "r"(mbar), "r"(cnt) : "memory");
}
__device__ __forceinline__ void mbar_expect_tx(uint32_t mbar, uint32_t bytes) {
    asm volatile("mbarrier.arrive.expect_tx.shared.b64 _, [%0], %1;"
                 :: "r"(mbar), "r"(bytes) : "memory");
}
__device__ __forceinline__ void bulk_load(uint32_t dst, const void* src,
                                          uint32_t bytes, uint32_t mbar) {
    asm volatile(
        "cp.async.bulk.shared::cta.global.mbarrier::complete_tx::bytes "
        "[%0], [%1], %2, [%3];"
        :: "r"(dst), "l"(src), "r"(bytes), "r"(mbar) : "memory");
}
__device__ __forceinline__ void mbar_wait(uint32_t mbar, uint32_t parity) {
    uint32_t done;
    asm volatile(
        "{\n\t.reg .pred p;\n\t"
        "mbarrier.try_wait.parity.acquire.cta.shared::cta.b64 p, [%1], %2;\n\t"
        "selp.b32 %0, 1, 0, p;\n\t}"
        : "=r"(done) : "r"(mbar), "r"(parity) : "memory");
    if (!done) {
        asm volatile(
            "{\n\t.reg .pred P1;\n\t"
            "WL_%=:\n\t"
            "mbarrier.try_wait.parity.acquire.cta.shared::cta.b64 P1, [%0], %1, 0x989680;\n\t"
            "@P1 bra.uni WD_%=;\n\t"
            "bra.uni WL_%=;\n\t"
            "WD_%=:\n\t}"
            :: "r"(mbar), "r"(parity) : "memory");
    }
}

// ---------------------------------------------------------------------------
// Setup (ONE launch):
//  blocks [0,64): TMA-pipelined prefix, one n per block. Double-buffered
//    cp.async.bulk loads of 16KB k-groups (contiguous per n — no tensor map),
//    running fp32 prefix in registers across groups (no chunk-sum exchange),
//    half2 stores to the table. Async-proxy loads bypass the LSU MLP cap
//    that limited the old chunk kernel to 2.4 TB/s.
//  blocks [64,1088): analytic search (uniform grid guess + exact verify walk)
//    -> g_SF. Uses no SMEM; overlaps with the prefix wave.
// ---------------------------------------------------------------------------
extern __shared__ __align__(128) unsigned char dynsmem[];

__global__ void __launch_bounds__(256)
setup_kernel(const float* __restrict__ X,
             const float* __restrict__ bnd,
             const float* __restrict__ weight,
             const float* __restrict__ bias) {
    if (blockIdx.x < PREFIX_BLOCKS) {
        float2* buf = (float2*)dynsmem;                 // [2][GROUP_K*256] float2
        uint32_t mb0 = smem_u32(dynsmem + 2 * GBYTES);
        uint32_t mb1 = mb0 + 8;
        const int n  = blockIdx.x;
        const int eg = threadIdx.x;                     // float2 column 0..255

        const char* wsrc = (const char*)(weight + (size_t)n * KDIM * EDIM);

        if (threadIdx.x == 0) {
            mbar_init(mb0, 1);
            mbar_init(mb1, 1);
        }
        __syncthreads();

        // Prologue: issue groups 0 and 1
        if (threadIdx.x == 0) {
            mbar_expect_tx(mb0, GBYTES);
            bulk_load(smem_u32(buf), wsrc, GBYTES, mb0);
            mbar_expect_tx(mb1, GBYTES);
            bulk_load(smem_u32(buf + GROUP_K * 256), wsrc + GBYTES, GBYTES, mb1);
        }

        float2 acc = ((const float2*)(bias + (size_t)n * EDIM))[eg];
        unsigned* Tn = (unsigned*)g_T16 + (size_t)n * BROW * (EDIM / 2) + eg;

        for (int g = 0; g < NGROUPS; g++) {
            const int p = g & 1;
            mbar_wait(p ? mb1 : mb0, (g >> 1) & 1);

            const float2* bp = buf + p * (GROUP_K * 256);
#pragma unroll
            for (int j = 0; j < GROUP_K; j++) {
                const int k = g * GROUP_K + j;
                __half2 h = __floats2half2_rn(acc.x, acc.y);
                Tn[(size_t)k * (EDIM / 2)] = *(unsigned*)&h;
                float2 w = bp[j * 256 + eg];
                acc.x += w.x; acc.y += w.y;
            }
            __syncthreads();                            // buffer p free

            if (threadIdx.x == 0 && g + 2 < NGROUPS) {
                uint32_t mb = p ? mb1 : mb0;
                mbar_expect_tx(mb, GBYTES);
                bulk_load(smem_u32(buf + p * (GROUP_K * 256)),
                          wsrc + (size_t)(g + 2) * GBYTES, GBYTES, mb);
            }
        }
        {   // final row k = KDIM
            __half2 h = __floats2half2_rn(acc.x, acc.y);
            Tn[(size_t)KDIM * (EDIM / 2)] = *(unsigned*)&h;
        }
    } else {
        const int i = (blockIdx.x - PREFIX_BLOCKS) * 256 + threadIdx.x; // b*N+n
        const int n = i & (NDIM - 1);
        const float x = X[i];                          // coalesced
        const float* bn = bnd + (size_t)n * BROW;

        // Analytic guess on the uniform grid, then exact verification walk.
        int lo = (int)ceilf(x * (float)KDIM) - 1;
        lo = lo < 0 ? 0 : (lo > KDIM - 1 ? KDIM - 1 : lo);
        while (lo < KDIM - 1 && __ldg(&bn[lo + 1]) < x) ++lo;
        while (lo > 0 && __ldg(&bn[lo]) >= x) --lo;

        const float s  = __ldg(&bn[lo]);
        const float eb = __ldg(&bn[lo + 1]);
        g_SF[i] = make_float2((x - s) / (eb - s + EPS_F), __int_as_float(lo));
    }
}

// ---------------------------------------------------------------------------
// Gather (proven 86us config — UNCHANGED): one warp per (b,n). Front-batched
// table LDG.128s, fp32 lerp, STS to this warp's 2KB SMEM slot, one per-warp
// cp.async.bulk TMA store. __syncwarp only.
// ---------------------------------------------------------------------------
__global__ void gather_kernel(float* __restrict__ out) {
    __shared__ float4 sm[8][EDIM / 4];                 // 8 x 2KB = 16KB

    const int lane = threadIdx.x & 31;
    const int warp = threadIdx.x >> 5;
    const int n = blockIdx.y;
    const int b = blockIdx.x * 8 + warp;

    const float2 sf = __ldg(&g_SF[(size_t)b * NDIM + n]);
    const float frac = sf.x;
    const int   lo   = __float_as_int(sf.y);

    const uint4* T0 = (const uint4*)(g_T16 + ((size_t)n * BROW + lo) * EDIM);
    const uint4* T1 = T0 + (EDIM / 8);

    uint4 a0 = __ldg(&T0[lane]);
    uint4 c0 = __ldg(&T1[lane]);
    uint4 a1 = __ldg(&T0[lane + 32]);
    uint4 c1 = __ldg(&T1[lane + 32]);

#pragma unroll
    for (int j = 0; j < 2; j++) {
        const uint4& a  = j ? a1 : a0;
        const uint4& cc = j ? c1 : c0;
        const unsigned* ap = &a.x;
        const unsigned* cp = &cc.x;
        float4 r0, r1;
#pragma unroll
        for (int q = 0; q < 4; q++) {
            float2 av = __half22float2(*(const __half2*)&ap[q]);
            float2 cv = __half22float2(*(const __half2*)&cp[q]);
            float v0 = fmaxf(fmaf(frac, cv.x - av.x, av.x), 0.0f);
            float v1 = fmaxf(fmaf(frac, cv.y - av.y, av.y), 0.0f);
            if (q == 0)      { r0.x = v0; r0.y = v1; }
            else if (q == 1) { r0.z = v0; r0.w = v1; }
            else if (q == 2) { r1.x = v0; r1.y = v1; }
            else             { r1.z = v0; r1.w = v1; }
        }
        const int i = lane + 32 * j;
        sm[warp][2 * i]     = r0;
        sm[warp][2 * i + 1] = r1;
    }

    __syncwarp();

    if (lane == 0) {
        float* gdst = out + ((size_t)b * NDIM + n) * EDIM;
        uint32_t saddr = smem_u32(&sm[warp][0]);
        asm volatile("fence.proxy.async.shared::cta;" ::: "memory");
        asm volatile(
            "cp.async.bulk.global.shared::cta.bulk_group [%0], [%1], %2;"
            :: "l"(gdst), "r"(saddr), "r"((int)(EDIM * 4)) : "memory");
        asm volatile("cp.async.bulk.commit_group;" ::: "memory");
        asm volatile("cp.async.bulk.wait_group 0;" ::: "memory");
    }
}

extern "C" void kernel_launch(void* const* d_in, const int* in_sizes, int n_in,
                              void* d_out, int out_size) {
    const float* X      = (const float*)d_in[0];   // (B, N)
    const float* bnd    = (const float*)d_in[1];   // (N, K+1)
    const float* weight = (const float*)d_in[2];   // (N, K, E)
    const float* bias   = (const float*)d_in[3];   // (N, E)
    float* out = (float*)d_out;                    // (B, N, E)

    setup_kernel<<<PREFIX_BLOCKS + SEARCH_BLOCKS, 256, SMEM_DYN>>>(X, bnd, weight, bias);

    dim3 grid(BDIM / 8, NDIM);
    gather_kernel<<<grid, 256>>>(out);
}

// round 17
// speedup vs baseline: 1.0142x; 1.0142x over previous
#include <cuda_runtime.h>
#include <cuda_fp16.h>
#include <cstdint>

// Problem dims (fixed): X:(B,N), boundaries:(N,K+1), weight:(N,K,E), bias:(N,E)
#define BDIM 4096
#define NDIM 64
#define KDIM 128
#define EDIM 512
#define EPS_F 1e-8f
#define NCHUNK 16
#define CHK (KDIM / NCHUNK)          // 8
#define BROW (KDIM + 1)              // 129

#define SLAB_BYTES (CHK * EDIM * 4)  // 16 KB contiguous (n,c) slab
#define SMEM_DYN (SLAB_BYTES + 16)   // slab + mbarrier

// Prefix table T[n][k][e] (fp16): T[n][k][e] = bias[n][e] + sum_{j<k} w[n][j][e]
// out[b][n][e] = relu( lerp(T[n][bidx], T[n][bidx+1], frac) )
__device__ __half g_T16[(size_t)NDIM * BROW * EDIM];
// Per-(b,n) (frac, bidx), indexed b*N+n.
__device__ float2 g_SF[(size_t)BDIM * NDIM];
// Chunk sums: S[n][c][eg2] as float2 (2MB)
__device__ float2 g_S2[(size_t)NDIM * NCHUNK * (EDIM / 2)];

#define CHUNK_BLOCKS  (NDIM * NCHUNK)                  // 1024 (one (n,c) slab each)
#define SEARCH_BLOCKS ((BDIM * NDIM) / 256)            // 1024

__device__ __forceinline__ uint32_t smem_u32(const void* p) {
    uint32_t a;
    asm("{ .reg .u64 t; cvta.to.shared.u64 t, %1; cvt.u32.u64 %0, t; }"
        : "=r"(a) : "l"(p));
    return a;
}
__device__ __forceinline__ void mbar_init(uint32_t mbar, uint32_t cnt) {
    asm volatile("mbarrier.init.shared.b64 [%0], %1;" :: "r"(mbar), "r"(cnt) : "memory");
}
__device__ __forceinline__ void mbar_expect_tx(uint32_t mbar, uint32_t bytes) {
    asm volatile("mbarrier.arrive.expect_tx.shared.b64 _, [%0], %1;"
                 :: "r"(mbar), "r"(bytes) : "memory");
}
__device__ __forceinline__ void bulk_load(uint32_t dst, const void* src,
                                          uint32_t bytes, uint32_t mbar) {
    asm volatile(
        "cp.async.bulk.shared::cta.global.mbarrier::complete_tx::bytes "
        "[%0], [%1], %2, [%3];"
        :: "r"(dst), "l"(src), "r"(bytes), "r"(mbar) : "memory");
}
__device__ __forceinline__ void mbar_wait(uint32_t mbar, uint32_t parity) {
    uint32_t done;
    asm volatile(
        "{\n\t.reg .pred p;\n\t"
        "mbarrier.try_wait.parity.acquire.cta.shared::cta.b64 p, [%1], %2;\n\t"
        "selp.b32 %0, 1, 0, p;\n\t}"
        : "=r"(done) : "r"(mbar), "r"(parity) : "memory");
    if (!done) {
        asm volatile(
            "{\n\t.reg .pred P1;\n\t"
            "WL_%=:\n\t"
            "mbarrier.try_wait.parity.acquire.cta.shared::cta.b64 P1, [%0], %1, 0x989680;\n\t"
            "@P1 bra.uni WD_%=;\n\t"
            "bra.uni WL_%=;\n\t"
            "WD_%=:\n\t}"
            :: "r"(mbar), "r"(parity) : "memory");
    }
}

extern __shared__ __align__(128) unsigned char dynsmem[];

// ---------------------------------------------------------------------------
// Setup A (fused):
//  blocks [0,1024): chunk sums via TMA. Block = (n,c): ONE cp.async.bulk of
//    the contiguous 16KB slab (async proxy — bypasses the LSU MLP cap that
//    held LDG at 2.4 TB/s), mbarrier wait, 8 conflict-free LDS per thread,
//    sum -> g_S2 (same layout as the proven scan consumes).
//  blocks [1024,2048): analytic search (uniform-grid guess + exact verify
//    walk) -> g_SF. No SMEM; overlaps the chunk wave.
// ---------------------------------------------------------------------------
__global__ void __launch_bounds__(256)
setup_a_kernel(const float* __restrict__ X,
               const float* __restrict__ bnd,
               const float* __restrict__ weight) {
    if (blockIdx.x < CHUNK_BLOCKS) {
        float2* buf = (float2*)dynsmem;                 // CHK*256 float2 = 16KB
        uint32_t mb = smem_u32(dynsmem + SLAB_BYTES);

        if (threadIdx.x == 0) mbar_init(mb, 1);
        __syncthreads();

        if (threadIdx.x == 0) {
            const char* wsrc = (const char*)weight + (size_t)blockIdx.x * SLAB_BYTES;
            mbar_expect_tx(mb, SLAB_BYTES);
            bulk_load(smem_u32(buf), wsrc, SLAB_BYTES, mb);
        }
        mbar_wait(mb, 0);

        const int eg = threadIdx.x;                     // float2 col 0..255
        float2 s = buf[eg];
#pragma unroll
        for (int j = 1; j < CHK; j++) {
            float2 w = buf[j * 256 + eg];
            s.x += w.x; s.y += w.y;
        }
        g_S2[blockIdx.x * 256 + eg] = s;                // ((n*16+c)*256+eg2)
    } else {
        const int i = (blockIdx.x - CHUNK_BLOCKS) * 256 + threadIdx.x; // b*N+n
        const int n = i & (NDIM - 1);
        const float x = X[i];                           // coalesced
        const float* bn = bnd + (size_t)n * BROW;

        // Analytic guess on the uniform grid, then exact verification walk.
        int lo = (int)ceilf(x * (float)KDIM) - 1;
        lo = lo < 0 ? 0 : (lo > KDIM - 1 ? KDIM - 1 : lo);
        while (lo < KDIM - 1 && __ldg(&bn[lo + 1]) < x) ++lo;
        while (lo > 0 && __ldg(&bn[lo]) >= x) --lo;

        const float s  = __ldg(&bn[lo]);
        const float eb = __ldg(&bn[lo + 1]);
        g_SF[i] = make_float2((x - s) / (eb - s + EPS_F), __int_as_float(lo));
    }
}

// ---------------------------------------------------------------------------
// Setup B: pure scan (proven 2.6us — UNCHANGED). Thread (n, c, eg2): base =
// bias + lower chunk sums (front-batched L2-hot loads), 8-step scan over
// L2-hot weight, packed half2 stores.
// ---------------------------------------------------------------------------
__global__ void __launch_bounds__(256)
setup_b_kernel(const float* __restrict__ weight,
               const float* __restrict__ bias) {
    int t = blockIdx.x * blockDim.x + threadIdx.x;
    int eg  = t & 255;
    int tmp = t >> 8;
    int c   = tmp & 15;
    int n   = tmp >> 4;

    const float2* Sp = g_S2 + ((size_t)n * NCHUNK) * (EDIM / 2) + eg;
    const int k0 = c * CHK;
    const float2* wp = (const float2*)(weight + (size_t)n * KDIM * EDIM)
                     + (size_t)k0 * (EDIM / 2) + eg;

    float2 sc[NCHUNK - 1];
#pragma unroll
    for (int cc = 0; cc < NCHUNK - 1; cc++)            // L2-hot, front-batched
        sc[cc] = Sp[(size_t)cc * (EDIM / 2)];

    float2 w[CHK];
#pragma unroll
    for (int j = 0; j < CHK; j++)                      // L2-hot, front-batched
        w[j] = wp[(size_t)j * (EDIM / 2)];

    float2 acc = ((const float2*)(bias + (size_t)n * EDIM))[eg];
#pragma unroll
    for (int cc = 0; cc < NCHUNK - 1; cc++) {
        if (cc < c) { acc.x += sc[cc].x; acc.y += sc[cc].y; }
    }

    unsigned* Tp = (unsigned*)g_T16 + ((size_t)n * BROW + k0) * (EDIM / 2) + eg;
#pragma unroll
    for (int j = 0; j < CHK; j++) {
        __half2 h = __floats2half2_rn(acc.x, acc.y);
        Tp[(size_t)j * (EDIM / 2)] = *(unsigned*)&h;
        acc.x += w[j].x; acc.y += w[j].y;
    }
    if (c == NCHUNK - 1) {
        __half2 h = __floats2half2_rn(acc.x, acc.y);
        Tp[(size_t)CHK * (EDIM / 2)] = *(unsigned*)&h;
    }
}

// ---------------------------------------------------------------------------
// Gather (proven 86us config — UNCHANGED): one warp per (b,n). Front-batched
// table LDG.128s, fp32 lerp, STS to this warp's 2KB SMEM slot, one per-warp
// cp.async.bulk TMA store. __syncwarp only.
// ---------------------------------------------------------------------------
__global__ void gather_kernel(float* __restrict__ out) {
    __shared__ float4 sm[8][EDIM / 4];                 // 8 x 2KB = 16KB

    const int lane = threadIdx.x & 31;
    const int warp = threadIdx.x >> 5;
    const int n = blockIdx.y;
    const int b = blockIdx.x * 8 + warp;

    const float2 sf = __ldg(&g_SF[(size_t)b * NDIM + n]);
    const float frac = sf.x;
    const int   lo   = __float_as_int(sf.y);

    const uint4* T0 = (const uint4*)(g_T16 + ((size_t)n * BROW + lo) * EDIM);
    const uint4* T1 = T0 + (EDIM / 8);

    uint4 a0 = __ldg(&T0[lane]);
    uint4 c0 = __ldg(&T1[lane]);
    uint4 a1 = __ldg(&T0[lane + 32]);
    uint4 c1 = __ldg(&T1[lane + 32]);

#pragma unroll
    for (int j = 0; j < 2; j++) {
        const uint4& a  = j ? a1 : a0;
        const uint4& cc = j ? c1 : c0;
        const unsigned* ap = &a.x;
        const unsigned* cp = &cc.x;
        float4 r0, r1;
#pragma unroll
        for (int q = 0; q < 4; q++) {
            float2 av = __half22float2(*(const __half2*)&ap[q]);
            float2 cv = __half22float2(*(const __half2*)&cp[q]);
            float v0 = fmaxf(fmaf(frac, cv.x - av.x, av.x), 0.0f);
            float v1 = fmaxf(fmaf(frac, cv.y - av.y, av.y), 0.0f);
            if (q == 0)      { r0.x = v0; r0.y = v1; }
            else if (q == 1) { r0.z = v0; r0.w = v1; }
            else if (q == 2) { r1.x = v0; r1.y = v1; }
            else             { r1.z = v0; r1.w = v1; }
        }
        const int i = lane + 32 * j;
        sm[warp][2 * i]     = r0;
        sm[warp][2 * i + 1] = r1;
    }

    __syncwarp();

    if (lane == 0) {
        float* gdst = out + ((size_t)b * NDIM + n) * EDIM;
        uint32_t saddr = smem_u32(&sm[warp][0]);
        asm volatile("fence.proxy.async.shared::cta;" ::: "memory");
        asm volatile(
            "cp.async.bulk.global.shared::cta.bulk_group [%0], [%1], %2;"
            :: "l"(gdst), "r"(saddr), "r"((int)(EDIM * 4)) : "memory");
        asm volatile("cp.async.bulk.commit_group;" ::: "memory");
        asm volatile("cp.async.bulk.wait_group 0;" ::: "memory");
    }
}

extern "C" void kernel_launch(void* const* d_in, const int* in_sizes, int n_in,
                              void* d_out, int out_size) {
    const float* X      = (const float*)d_in[0];   // (B, N)
    const float* bnd    = (const float*)d_in[1];   // (N, K+1)
    const float* weight = (const float*)d_in[2];   // (N, K, E)
    const float* bias   = (const float*)d_in[3];   // (N, E)
    float* out = (float*)d_out;                    // (B, N, E)

    setup_a_kernel<<<CHUNK_BLOCKS + SEARCH_BLOCKS, 256, SMEM_DYN>>>(X, bnd, weight);
    setup_b_kernel<<<CHUNK_BLOCKS, 256>>>(weight, bias);

    dim3 grid(BDIM / 8, NDIM);
    gather_kernel<<<grid, 256>>>(out);
}